// round 16
// baseline (speedup 1.0000x reference)
#include <cuda_runtime.h>
#include <cuda_bf16.h>
#include <mma.h>
#include <cstdint>
#include <cstddef>

using namespace nvcuda;
typedef __nv_bfloat16 bf16;

#define NB   256
#define TT   120
#define HH   256
#define G4   1024
#define BT   30720   // NB*TT
#define DIN  38
#define NCTA 148     // 1 CTA per SM, all wave-1 resident
#define NTILE 352    // 224 stage1 + 112 stage2 + 16 stage0 (tiles are 128x128)

// padded smem strides (bank-conflict-free)
#define ASTR 72      // As row stride bf16 (144B; row delta mod 128B = 16 -> walks banks)
#define BSTR 136     // Bs row stride bf16 (272B; delta mod 128B = 16)
#define ZSTR 132     // Z row stride floats
#define AS_STAGE (128 * ASTR)           // 9216 bf16 per stage
#define BS_STAGE (64 * BSTR)            // 8704 bf16 per stage
#define BS_BASE  (2 * AS_STAGE)         // 18432 bf16 offset
#define SMEM_BYTES 72192                // max(71680 staging, 67584 Z) padded

// ---------------- scratch (device globals) ----------------
static __device__ __align__(16) float g_xw_eco[(size_t)BT * G4];
static __device__ __align__(16) bf16  g_xeb[(size_t)BT * HH];
static __device__ __align__(16) bf16  g_oab[(size_t)14 * BT * HH];
static __device__ __align__(16) float g_hts[(size_t)7 * 2560 * HH];
static __device__ __align__(16) float g_d1[(size_t)7 * 2560 * 256];
static __device__ __align__(16) float g_d2[(size_t)7 * 2560 * 64];
static __device__ __align__(16) bf16  g_hb[22][2][NB * HH];
static __device__ __align__(16) float g_c[22][NB * HH];
static __device__ __align__(16) bf16  g_pk0[(size_t)256 * G4];          // eco U, [k][n1024]
static __device__ __align__(16) bf16  g_pk1[(size_t)14 << 19];          // data+att [z][k512][n1024]
static __device__ __align__(16) bf16  g_pk2[(size_t)7 << 19];           // ts
static __device__ volatile unsigned g_barGen;
static __device__ unsigned g_barCnt;
static __device__ unsigned g_tileCnt[2];

__constant__ float LS_MAX_c[7] = {-1.0516589f, -0.64791672f, -0.99871467f,
                                  -0.86651843f, -0.72868288f, -0.72231681f, -0.78230592f};

__device__ __forceinline__ float tanha(float x) {
    float y; asm("tanh.approx.f32 %0, %1;" : "=f"(y) : "f"(x)); return y;
}
__device__ __forceinline__ float sigm(float x) { return fmaf(tanha(0.5f * x), 0.5f, 0.5f); }

// ---------------- init ----------------
__global__ void k_zero() {
    size_t i = (size_t)blockIdx.x * blockDim.x + threadIdx.x;
    size_t stride = (size_t)gridDim.x * blockDim.x;
    bf16* h = &g_hb[0][0][0];
    float* c = &g_c[0][0];
    const size_t nh = (size_t)22 * 2 * NB * HH, nc = (size_t)22 * NB * HH;
    for (size_t k = i; k < nh; k += stride) h[k] = __float2bfloat16(0.f);
    for (size_t k = i; k < nc; k += stride) c[k] = 0.f;
    if (i == 0) { g_barCnt = 0; g_barGen = 0; g_tileCnt[0] = 0; g_tileCnt[1] = 0; }
}

// ---------------- unified weight packing (fp32 -> bf16, [U;W] along K, k-major) ----------------
__device__ __forceinline__ float pk_src(const float* U, const float* W, size_t i) {
    int n = (int)(i & 1023);
    int k = (int)((i >> 10) & 511);
    int z = (int)(i >> 19);
    return (k < 256) ? U[((size_t)z * 256 + k) * G4 + n]
                     : W[((size_t)z * 256 + (k - 256)) * G4 + n];
}
__global__ void k_packall(const float* __restrict__ eU,
                          const float* __restrict__ dU, const float* __restrict__ dW,
                          const float* __restrict__ aU, const float* __restrict__ aW,
                          const float* __restrict__ tU, const float* __restrict__ tW) {
    size_t i = (size_t)blockIdx.x * 256 + threadIdx.x;
    const size_t n0 = (size_t)256 * G4;
    const size_t n1 = (size_t)7 << 19;
    if (i < n0) { g_pk0[i] = __float2bfloat16(eU[i]); return; }
    i -= n0;
    if (i < n1) { g_pk1[i] = __float2bfloat16(pk_src(dU, dW, i)); return; }
    i -= n1;
    if (i < n1) { g_pk1[n1 + i] = __float2bfloat16(pk_src(aU, aW, i)); return; }
    i -= n1;
    if (i < n1) { g_pk2[i] = __float2bfloat16(pk_src(tU, tW, i)); }
}

// ---------------- eco input projection ----------------
__global__ void __launch_bounds__(256) k_xw_eco(const float* __restrict__ inp,
                                                const float* __restrict__ W,
                                                const float* __restrict__ b) {
    int row0 = blockIdx.x * 8;
    __shared__ float a[8][16];
    int tid = threadIdx.x;
    if (tid < 128) {
        int r = tid >> 4, d = tid & 15;
        a[r][d] = inp[(size_t)(row0 + r) * DIN + d];
    }
    __syncthreads();
#pragma unroll
    for (int i = 0; i < 4; i++) {
        int col = tid + i * 256;
        float wv[16];
#pragma unroll
        for (int d = 0; d < 16; d++) wv[d] = W[d * G4 + col];
        float bias = b[col];
#pragma unroll
        for (int r = 0; r < 8; r++) {
            float s = bias;
#pragma unroll
            for (int d = 0; d < 16; d++) s += a[r][d] * wv[d];
            g_xw_eco[(size_t)(row0 + r) * G4 + col] = s;
        }
    }
}

// ---------------- grid barrier ----------------
__device__ __forceinline__ void gridbar(int u) {
    __syncthreads();
    if (threadIdx.x == 0) {
        __threadfence();
        unsigned gen = g_barGen;
        if (atomicAdd(&g_barCnt, 1u) == NCTA - 1) {
            g_barCnt = 0;
            g_tileCnt[(u + 1) & 1] = 0;
            __threadfence();
            g_barGen = gen + 1;
        } else {
            while (g_barGen == gen) { __nanosleep(64); }
        }
        __threadfence();
    }
    __syncthreads();
}

// ---------------- persistent pipelined LSTM kernel ----------------
// Tile: 128 batch rows x 128 packed cols (32 hidden x 4 gates), K=512 (256 eco), BK=64.
// 512 threads, 16 warps as 4(M) x 4(N), warp tile 32x32. Work-stealing across 148 CTAs.
__global__ void __launch_bounds__(512, 1) k_persist(const float* __restrict__ data_b,
                                                    const float* __restrict__ att_b,
                                                    const float* __restrict__ ts_b)
{
    extern __shared__ __align__(32) float smf[];   // 70.5KB dyn: As|Bs double-buffered; reused as Z
    __shared__ int sh_id;
    bf16* As = (bf16*)smf;
    bf16* Bs = (bf16*)smf + BS_BASE;
    int tid = threadIdx.x;
    int wid = tid >> 5, wm = wid >> 2, wn = wid & 3;

    using FA = wmma::fragment<wmma::matrix_a, 16, 16, 16, bf16, wmma::row_major>;
    using FB = wmma::fragment<wmma::matrix_b, 16, 16, 16, bf16, wmma::row_major>;
    using FC = wmma::fragment<wmma::accumulator, 16, 16, 16, float>;

    for (int u = 0; u < TT + 2; u++) {
        unsigned* cnt = &g_tileCnt[u & 1];
        while (true) {
            if (tid == 0) sh_id = (int)atomicAdd(cnt, 1u);
            __syncthreads();
            int id = sh_id;
            __syncthreads();
            if (id >= NTILE) break;

            int stage, jz, m0, g0, t;
            if (id < 224)      { stage = 1; jz = id >> 4; int r = id & 15;
                                 m0 = (r >> 3) * 128; g0 = (r & 7) * 32; t = u - 1; }
            else if (id < 336) { stage = 2; int i2 = id - 224; jz = i2 >> 4; int r = i2 & 15;
                                 m0 = (r >> 3) * 128; g0 = (r & 7) * 32; t = u - 2; }
            else               { stage = 0; int i0 = id - 336; jz = 0;
                                 m0 = (i0 >> 3) * 128; g0 = (i0 & 7) * 32; t = u; }
            if (t < 0 || t >= TT) continue;

            int slot = (stage == 0) ? 0 : (stage == 1 ? 1 + jz : 15 + jz);
            const bf16* hin = g_hb[slot][t & 1];
            bf16* hout = g_hb[slot][(t + 1) & 1];
            float* cst = g_c[slot];
            const bf16* Bw = (stage == 0) ? g_pk0
                           : (stage == 1) ? g_pk1 + ((size_t)jz << 19)
                                          : g_pk2 + ((size_t)jz << 19);
            bool sig = (stage == 1 && jz >= 7);
            const float* bias = (stage == 1)
                ? (jz < 7 ? data_b + jz * G4 : att_b + (jz - 7) * G4)
                : (stage == 2 ? ts_b + jz * G4 : nullptr);
            int KT = (stage == 0) ? 4 : 8;   // BK=64 chunks

            // A: 128x64 bf16 = 1024 uint4 -> 2 units/thread (unit = tid + r*512)
            //    row = unit>>3 (0..127), kin = (unit&7)*8
            // B: 64x128 bf16 = 1024 uint4 -> 2 units/thread
            //    kr = unit>>4 (0..63), cc = unit&15
            auto ldA1 = [&](int k0, int unit) -> uint4 {
                int row = m0 + (unit >> 3), k = k0 + (unit & 7) * 8;
                if (stage == 0 || k < 256)
                    return *(const uint4*)&hin[(size_t)row * HH + k];
                size_t base = ((size_t)row * TT + t) * HH + (k - 256);
                if (stage == 1)
                    return *(const uint4*)&g_xeb[base];
                uint4 o = *(const uint4*)&g_oab[(size_t)jz * BT * HH + base];
                uint4 a = *(const uint4*)&g_oab[(size_t)(jz + 7) * BT * HH + base];
                __nv_bfloat162* op = (__nv_bfloat162*)&o;
                __nv_bfloat162* ap = (__nv_bfloat162*)&a;
                op[0] = __hmul2(op[0], ap[0]); op[1] = __hmul2(op[1], ap[1]);
                op[2] = __hmul2(op[2], ap[2]); op[3] = __hmul2(op[3], ap[3]);
                return o;
            };
            auto ldB1 = [&](int k0, int unit) -> uint4 {
                int kr = unit >> 4, cc = unit & 15;
                size_t coff = (size_t)(cc >> 2) * HH + g0 + (cc & 3) * 8;
                return *(const uint4*)&Bw[(size_t)(k0 + kr) * G4 + coff];
            };
            auto stA1 = [&](int buf, int unit, uint4 v) {
                *(uint4*)&As[buf * AS_STAGE + (unit >> 3) * ASTR + (unit & 7) * 8] = v;
            };
            auto stB1 = [&](int buf, int unit, uint4 v) {
                *(uint4*)&Bs[buf * BS_STAGE + (unit >> 4) * BSTR + (unit & 15) * 8] = v;
            };

            FC acc[2][2];
#pragma unroll
            for (int i = 0; i < 2; i++)
#pragma unroll
                for (int j = 0; j < 2; j++) wmma::fill_fragment(acc[i][j], 0.f);

            {
                uint4 a0 = ldA1(0, tid), a1 = ldA1(0, tid + 512);
                uint4 b0 = ldB1(0, tid), b1 = ldB1(0, tid + 512);
                stA1(0, tid, a0); stA1(0, tid + 512, a1);
                stB1(0, tid, b0); stB1(0, tid + 512, b1);
            }
            __syncthreads();
            for (int kt = 0; kt < KT; kt++) {
                uint4 a0, a1, b0, b1;
                if (kt + 1 < KT) {
                    int k0 = (kt + 1) * 64;
                    a0 = ldA1(k0, tid); a1 = ldA1(k0, tid + 512);
                    b0 = ldB1(k0, tid); b1 = ldB1(k0, tid + 512);
                }
                int buf = kt & 1;
#pragma unroll
                for (int ks = 0; ks < 4; ks++) {
                    FA fa[2]; FB fb[2];
#pragma unroll
                    for (int i = 0; i < 2; i++)
                        wmma::load_matrix_sync(fa[i],
                            &As[buf * AS_STAGE + (wm * 32 + 16 * i) * ASTR + ks * 16], ASTR);
#pragma unroll
                    for (int j = 0; j < 2; j++)
                        wmma::load_matrix_sync(fb[j],
                            &Bs[buf * BS_STAGE + (ks * 16) * BSTR + wn * 32 + 16 * j], BSTR);
#pragma unroll
                    for (int i = 0; i < 2; i++)
#pragma unroll
                        for (int j = 0; j < 2; j++)
                            wmma::mma_sync(acc[i][j], fa[i], fb[j], acc[i][j]);
                }
                if (kt + 1 < KT) {
                    int nb = 1 - buf;
                    stA1(nb, tid, a0); stA1(nb, tid + 512, a1);
                    stB1(nb, tid, b0); stB1(nb, tid + 512, b1);
                }
                __syncthreads();
            }
#pragma unroll
            for (int i = 0; i < 2; i++)
#pragma unroll
                for (int j = 0; j < 2; j++)
                    wmma::store_matrix_sync(&smf[(wm * 32 + 16 * i) * ZSTR + wn * 32 + 16 * j],
                                            acc[i][j], ZSTR, wmma::mem_row_major);
            __syncthreads();

            int u2 = tid & 31, rr = tid >> 5;   // rr 0..15 -> 8 rows each = 128 rows
#pragma unroll
            for (int s = 0; s < 8; s++) {
                int r = rr * 8 + s;
                int brow = m0 + r;
                float zi, zf, zg, zo;
                if (stage == 0) {
                    size_t xb = ((size_t)brow * TT + t) * G4 + g0 + u2;
                    zi = smf[r * ZSTR + u2]      + g_xw_eco[xb];
                    zf = smf[r * ZSTR + 32 + u2] + g_xw_eco[xb + 256];
                    zg = smf[r * ZSTR + 64 + u2] + g_xw_eco[xb + 512];
                    zo = smf[r * ZSTR + 96 + u2] + g_xw_eco[xb + 768];
                } else {
                    zi = smf[r * ZSTR + u2]      + bias[g0 + u2];
                    zf = smf[r * ZSTR + 32 + u2] + bias[g0 + u2 + 256];
                    zg = smf[r * ZSTR + 64 + u2] + bias[g0 + u2 + 512];
                    zo = smf[r * ZSTR + 96 + u2] + bias[g0 + u2 + 768];
                }
                float gi = sigm(zi), gf = sigm(zf), go = sigm(zo);
                size_t sidx = (size_t)brow * HH + g0 + u2;
                float cn = gf * cst[sidx] + gi * (sig ? sigm(zg) : tanha(zg));
                float hv = go * (sig ? sigm(cn) : tanha(cn));
                cst[sidx] = cn;
                hout[sidx] = __float2bfloat16(hv);
                size_t seq = ((size_t)brow * TT + t) * HH + g0 + u2;
                if (stage == 0) {
                    g_xeb[seq] = __float2bfloat16(hv);
                } else if (stage == 1) {
                    g_oab[(size_t)jz * BT * HH + seq] = __float2bfloat16(hv);
                } else if (t % 12 == 11) {
                    g_hts[((size_t)jz * 2560 + (size_t)brow * 10 + t / 12) * HH + g0 + u2] = hv;
                }
            }
            __syncthreads();
        }
        gridbar(u);
    }
}

// ---------------- tf32 wmma GEMM (relu) for d1/d2 ----------------
__global__ void __launch_bounds__(256) k_gemm(
    const float* __restrict__ A, size_t aStride,
    const float* __restrict__ Bw, size_t bStride,
    const float* __restrict__ bias, int biasStride,
    float* __restrict__ C, size_t cStride, int N, int K)
{
    __shared__ __align__(16) float sm[8192];
    float* As = sm;
    float* Bs = sm + 4096;
    int tid = threadIdx.x, zi = blockIdx.z;
    A += (size_t)zi * aStride;
    Bw += (size_t)zi * bStride;
    bias += (size_t)zi * biasStride;
    C += (size_t)zi * cStride;
    int m0 = blockIdx.y * 128, n0 = blockIdx.x * 64;
    int arow = tid >> 2, akc = (tid & 3) * 4;
    int brow = tid >> 4, bcol = (tid & 15) * 4;

    using FA = wmma::fragment<wmma::matrix_a, 16, 16, 8, wmma::precision::tf32, wmma::row_major>;
    using FB = wmma::fragment<wmma::matrix_b, 16, 16, 8, wmma::precision::tf32, wmma::row_major>;
    using FC = wmma::fragment<wmma::accumulator, 16, 16, 8, float>;
    FC acc[2][2];
#pragma unroll
    for (int i = 0; i < 2; i++)
#pragma unroll
        for (int j = 0; j < 2; j++) wmma::fill_fragment(acc[i][j], 0.f);
    int wid = tid >> 5, wm = wid >> 1, wn = wid & 1;

    {
        float4 a0 = *(const float4*)&A[(size_t)(m0 + arow) * K + akc];
        float4 a1 = *(const float4*)&A[(size_t)(m0 + arow + 64) * K + akc];
        float4 b0 = *(const float4*)&Bw[(size_t)brow * N + n0 + bcol];
        *(float4*)&As[arow * 16 + akc] = a0;
        *(float4*)&As[(arow + 64) * 16 + akc] = a1;
        *(float4*)&Bs[brow * 64 + bcol] = b0;
    }
    __syncthreads();
    int KT = K / 16;
    for (int kt = 0; kt < KT; kt++) {
        float4 a0, a1, b0;
        if (kt + 1 < KT) {
            int k0 = (kt + 1) * 16;
            a0 = *(const float4*)&A[(size_t)(m0 + arow) * K + k0 + akc];
            a1 = *(const float4*)&A[(size_t)(m0 + arow + 64) * K + k0 + akc];
            b0 = *(const float4*)&Bw[(size_t)(k0 + brow) * N + n0 + bcol];
        }
        int buf = kt & 1;
#pragma unroll
        for (int ks = 0; ks < 2; ks++) {
            FA fa[2]; FB fb[2];
#pragma unroll
            for (int i = 0; i < 2; i++) {
                wmma::load_matrix_sync(fa[i], &As[buf * 2048 + (wm * 32 + 16 * i) * 16 + ks * 8], 16);
#pragma unroll
                for (int e = 0; e < fa[i].num_elements; e++) fa[i].x[e] = wmma::__float_to_tf32(fa[i].x[e]);
            }
#pragma unroll
            for (int j = 0; j < 2; j++) {
                wmma::load_matrix_sync(fb[j], &Bs[buf * 1024 + (ks * 8) * 64 + wn * 32 + 16 * j], 64);
#pragma unroll
                for (int e = 0; e < fb[j].num_elements; e++) fb[j].x[e] = wmma::__float_to_tf32(fb[j].x[e]);
            }
#pragma unroll
            for (int i = 0; i < 2; i++)
#pragma unroll
                for (int j = 0; j < 2; j++) wmma::mma_sync(acc[i][j], fa[i], fb[j], acc[i][j]);
        }
        if (kt + 1 < KT) {
            int nb = 1 - buf;
            *(float4*)&As[nb * 2048 + arow * 16 + akc] = a0;
            *(float4*)&As[nb * 2048 + (arow + 64) * 16 + akc] = a1;
            *(float4*)&Bs[nb * 1024 + brow * 64 + bcol] = b0;
        }
        __syncthreads();
    }
#pragma unroll
    for (int i = 0; i < 2; i++)
#pragma unroll
        for (int j = 0; j < 2; j++)
            wmma::store_matrix_sync(&sm[(wm * 32 + 16 * i) * 64 + wn * 32 + 16 * j], acc[i][j], 64,
                                    wmma::mem_row_major);
    __syncthreads();
    int col = tid & 63, r0i = tid >> 6;
    float bv = bias[n0 + col];
#pragma unroll 8
    for (int s = 0; s < 32; s++) {
        int r = r0i + s * 4;
        float v = sm[r * 64 + col] + bv;
        C[(size_t)(m0 + r) * N + n0 + col] = fmaxf(v, 0.f);
    }
}

// ---------------- head ----------------
__global__ void k_head(const float* __restrict__ inp, const float* __restrict__ dfW,
                       const float* __restrict__ dfb, float* __restrict__ out) {
    int gid = blockIdx.x * blockDim.x + threadIdx.x;
    if (gid >= 2560 * 7) return;
    int j = gid % 7, bt = gid / 7, b = bt / 10;
    const float* w = dfW + j * 67;
    const float* v = &g_d2[((size_t)j * 2560 + bt) * 64];
    float s = dfb[j];
#pragma unroll 16
    for (int k = 0; k < 64; k++) s += v[k] * w[k];
    size_t base = ((size_t)b * TT + 11) * DIN;
    s += inp[base + 23] * w[64] + inp[base + 23 + j + 1] * w[65] + inp[base + 23 + j + 8] * w[66];
    s += inp[base + 16 + j];
    out[(size_t)bt * 7 + j] = fmaxf(s, LS_MAX_c[j]);
}

extern "C" void kernel_launch(void* const* d_in, const int* in_sizes, int n_in,
                              void* d_out, int out_size) {
    const float* inp    = (const float*)d_in[0];
    const float* eco_W  = (const float*)d_in[1];
    const float* eco_U  = (const float*)d_in[2];
    const float* eco_b  = (const float*)d_in[3];
    const float* data_W = (const float*)d_in[4];
    const float* data_U = (const float*)d_in[5];
    const float* data_b = (const float*)d_in[6];
    const float* att_W  = (const float*)d_in[7];
    const float* att_U  = (const float*)d_in[8];
    const float* att_b  = (const float*)d_in[9];
    const float* ts_W   = (const float*)d_in[10];
    const float* ts_U   = (const float*)d_in[11];
    const float* ts_b   = (const float*)d_in[12];
    const float* d1_W   = (const float*)d_in[13];
    const float* d1_b   = (const float*)d_in[14];
    const float* d2_W   = (const float*)d_in[15];
    const float* d2_b   = (const float*)d_in[16];
    const float* df_W   = (const float*)d_in[17];
    const float* df_b   = (const float*)d_in[18];
    float* out = (float*)d_out;

    float *hts, *d1, *d2;
    cudaGetSymbolAddress((void**)&hts, g_hts);
    cudaGetSymbolAddress((void**)&d1, g_d1);
    cudaGetSymbolAddress((void**)&d2, g_d2);

    cudaFuncSetAttribute(k_persist, cudaFuncAttributeMaxDynamicSharedMemorySize, SMEM_BYTES);

    // k_persist is the 4th launch (ncu capture window)
    k_zero<<<64, 256>>>();
    k_xw_eco<<<BT / 8, 256>>>(inp, eco_W, eco_b);
    k_packall<<<44032, 256>>>(eco_U, data_U, data_W, att_U, att_W, ts_U, ts_W);

    k_persist<<<NCTA, 512, SMEM_BYTES>>>(data_b, att_b, ts_b);

    k_gemm<<<dim3(4, 20, 7), 256>>>(hts, (size_t)2560 * HH, d1_W, (size_t)HH * 256,
                                    d1_b, 256, d1, (size_t)2560 * 256, 256, HH);
    k_gemm<<<dim3(1, 20, 7), 256>>>(d1, (size_t)2560 * 256, d2_W, (size_t)256 * 64,
                                    d2_b, 64, d2, (size_t)2560 * 64, 64, 256);
    k_head<<<70, 256>>>(inp, df_W, df_b, out);
}

// round 17
// speedup vs baseline: 1.1510x; 1.1510x over previous
#include <cuda_runtime.h>
#include <cuda_bf16.h>
#include <mma.h>
#include <cstdint>
#include <cstddef>

using namespace nvcuda;
typedef __nv_bfloat16 bf16;

#define NB   256
#define TT   120
#define HH   256
#define G4   1024
#define BT   30720   // NB*TT
#define DIN  38
#define NCTA 296     // 2 CTAs per SM (148 SMs), all wave-1 resident
#define NTILE 704    // 448 stage1 + 224 stage2 + 32 stage0

// padded smem strides (bank-conflict-free)
#define ASTR 72      // As row stride bf16 (144B; 16B-slot walk per row)
#define BSTR 136     // Bs row stride bf16 (272B)
#define ZSTR 132     // Z row stride floats
#define AS_STAGE (64 * ASTR)            // 4608 bf16
#define BS_STAGE (64 * BSTR)            // 8704 bf16
#define BS_BASE  (2 * AS_STAGE)         // 9216 bf16
#define SMEM_FLOATS 13312               // 53248 B total (dynamic)

// ---------------- scratch (device globals) ----------------
static __device__ __align__(16) float g_xw_eco[(size_t)BT * G4];
static __device__ __align__(16) bf16  g_xeb[(size_t)BT * HH];
static __device__ __align__(16) bf16  g_oab[(size_t)14 * BT * HH];
static __device__ __align__(16) float g_hts[(size_t)7 * 2560 * HH];
static __device__ __align__(16) float g_d1[(size_t)7 * 2560 * 256];
static __device__ __align__(16) float g_d2[(size_t)7 * 2560 * 64];
static __device__ __align__(16) bf16  g_hb[22][2][NB * HH];
static __device__ __align__(16) float g_c[22][NB * HH];
static __device__ __align__(16) bf16  g_pk0[(size_t)256 * G4];          // eco U, [k][n1024]
static __device__ __align__(16) bf16  g_pk1[(size_t)14 << 19];          // data+att [z][k512][n1024]
static __device__ __align__(16) bf16  g_pk2[(size_t)7 << 19];           // ts
static __device__ volatile unsigned g_barGen;
static __device__ unsigned g_barCnt;
static __device__ unsigned g_tileCnt[2];

__constant__ float LS_MAX_c[7] = {-1.0516589f, -0.64791672f, -0.99871467f,
                                  -0.86651843f, -0.72868288f, -0.72231681f, -0.78230592f};

__device__ __forceinline__ float tanha(float x) {
    float y; asm("tanh.approx.f32 %0, %1;" : "=f"(y) : "f"(x)); return y;
}
__device__ __forceinline__ float sigm(float x) { return fmaf(tanha(0.5f * x), 0.5f, 0.5f); }

// ---------------- init ----------------
__global__ void k_zero() {
    size_t i = (size_t)blockIdx.x * blockDim.x + threadIdx.x;
    size_t stride = (size_t)gridDim.x * blockDim.x;
    bf16* h = &g_hb[0][0][0];
    float* c = &g_c[0][0];
    const size_t nh = (size_t)22 * 2 * NB * HH, nc = (size_t)22 * NB * HH;
    for (size_t k = i; k < nh; k += stride) h[k] = __float2bfloat16(0.f);
    for (size_t k = i; k < nc; k += stride) c[k] = 0.f;
    if (i == 0) { g_barCnt = 0; g_barGen = 0; g_tileCnt[0] = 0; g_tileCnt[1] = 0; }
}

// ---------------- unified weight packing (fp32 -> bf16, [U;W] along K, k-major) ----------------
__device__ __forceinline__ float pk_src(const float* U, const float* W, size_t i) {
    int n = (int)(i & 1023);
    int k = (int)((i >> 10) & 511);
    int z = (int)(i >> 19);
    return (k < 256) ? U[((size_t)z * 256 + k) * G4 + n]
                     : W[((size_t)z * 256 + (k - 256)) * G4 + n];
}
__global__ void k_packall(const float* __restrict__ eU,
                          const float* __restrict__ dU, const float* __restrict__ dW,
                          const float* __restrict__ aU, const float* __restrict__ aW,
                          const float* __restrict__ tU, const float* __restrict__ tW) {
    size_t i = (size_t)blockIdx.x * 256 + threadIdx.x;
    const size_t n0 = (size_t)256 * G4;
    const size_t n1 = (size_t)7 << 19;
    if (i < n0) { g_pk0[i] = __float2bfloat16(eU[i]); return; }
    i -= n0;
    if (i < n1) { g_pk1[i] = __float2bfloat16(pk_src(dU, dW, i)); return; }
    i -= n1;
    if (i < n1) { g_pk1[n1 + i] = __float2bfloat16(pk_src(aU, aW, i)); return; }
    i -= n1;
    if (i < n1) { g_pk2[i] = __float2bfloat16(pk_src(tU, tW, i)); }
}

// ---------------- eco input projection ----------------
__global__ void __launch_bounds__(256) k_xw_eco(const float* __restrict__ inp,
                                                const float* __restrict__ W,
                                                const float* __restrict__ b) {
    int row0 = blockIdx.x * 8;
    __shared__ float a[8][16];
    int tid = threadIdx.x;
    if (tid < 128) {
        int r = tid >> 4, d = tid & 15;
        a[r][d] = inp[(size_t)(row0 + r) * DIN + d];
    }
    __syncthreads();
#pragma unroll
    for (int i = 0; i < 4; i++) {
        int col = tid + i * 256;
        float wv[16];
#pragma unroll
        for (int d = 0; d < 16; d++) wv[d] = W[d * G4 + col];
        float bias = b[col];
#pragma unroll
        for (int r = 0; r < 8; r++) {
            float s = bias;
#pragma unroll
            for (int d = 0; d < 16; d++) s += a[r][d] * wv[d];
            g_xw_eco[(size_t)(row0 + r) * G4 + col] = s;
        }
    }
}

// ---------------- grid barrier ----------------
__device__ __forceinline__ void gridbar(int u) {
    __syncthreads();
    if (threadIdx.x == 0) {
        __threadfence();
        unsigned gen = g_barGen;
        if (atomicAdd(&g_barCnt, 1u) == NCTA - 1) {
            g_barCnt = 0;
            g_tileCnt[(u + 1) & 1] = 0;
            __threadfence();
            g_barGen = gen + 1;
        } else {
            while (g_barGen == gen) { __nanosleep(64); }
        }
        __threadfence();
    }
    __syncthreads();
}

// ---------------- persistent pipelined LSTM kernel (work-stealing, BK=64, cp.async B) ----------------
__global__ void __launch_bounds__(256, 2) k_persist(const float* __restrict__ data_b,
                                                    const float* __restrict__ att_b,
                                                    const float* __restrict__ ts_b)
{
    extern __shared__ __align__(32) float smf[];   // 53.2KB dyn: As|Bs double-buffered; reused as Z
    __shared__ int sh_id;
    bf16* As = (bf16*)smf;
    int tid = threadIdx.x;
    int wid = tid >> 5, wm = wid >> 2, wn = wid & 3;
    uint32_t sbase;
    asm("{ .reg .u64 t; cvta.to.shared.u64 t, %1; cvt.u32.u64 %0, t; }"
        : "=r"(sbase) : "l"(smf));

    using FA = wmma::fragment<wmma::matrix_a, 16, 16, 16, bf16, wmma::row_major>;
    using FB = wmma::fragment<wmma::matrix_b, 16, 16, 16, bf16, wmma::row_major>;
    using FC = wmma::fragment<wmma::accumulator, 16, 16, 16, float>;

    for (int u = 0; u < TT + 2; u++) {
        unsigned* cnt = &g_tileCnt[u & 1];
        while (true) {
            if (tid == 0) sh_id = (int)atomicAdd(cnt, 1u);
            __syncthreads();
            int id = sh_id;
            __syncthreads();
            if (id >= NTILE) break;

            int stage, jz, m0, g0, t;
            if (id < 448)      { stage = 1; jz = id >> 5; int r = id & 31;
                                 m0 = (r >> 3) * 64; g0 = (r & 7) * 32; t = u - 1; }
            else if (id < 672) { stage = 2; int i2 = id - 448; jz = i2 >> 5; int r = i2 & 31;
                                 m0 = (r >> 3) * 64; g0 = (r & 7) * 32; t = u - 2; }
            else               { stage = 0; int i0 = id - 672; jz = 0;
                                 m0 = (i0 >> 3) * 64; g0 = (i0 & 7) * 32; t = u; }
            if (t < 0 || t >= TT) continue;

            int slot = (stage == 0) ? 0 : (stage == 1 ? 1 + jz : 15 + jz);
            const bf16* hin = g_hb[slot][t & 1];
            bf16* hout = g_hb[slot][(t + 1) & 1];
            float* cst = g_c[slot];
            const bf16* Bw = (stage == 0) ? g_pk0
                           : (stage == 1) ? g_pk1 + ((size_t)jz << 19)
                                          : g_pk2 + ((size_t)jz << 19);
            bool sig = (stage == 1 && jz >= 7);
            const float* bias = (stage == 1)
                ? (jz < 7 ? data_b + jz * G4 : att_b + (jz - 7) * G4)
                : (stage == 2 ? ts_b + jz * G4 : nullptr);
            int KT = (stage == 0) ? 4 : 8;   // BK=64 chunks

            auto ldA1 = [&](int k0, int unit) -> uint4 {
                int row = m0 + (unit >> 3), k = k0 + (unit & 7) * 8;
                if (stage == 0 || k < 256)
                    return *(const uint4*)&hin[(size_t)row * HH + k];
                size_t base = ((size_t)row * TT + t) * HH + (k - 256);
                if (stage == 1)
                    return *(const uint4*)&g_xeb[base];
                uint4 o = *(const uint4*)&g_oab[(size_t)jz * BT * HH + base];
                uint4 a = *(const uint4*)&g_oab[(size_t)(jz + 7) * BT * HH + base];
                __nv_bfloat162* op = (__nv_bfloat162*)&o;
                __nv_bfloat162* ap = (__nv_bfloat162*)&a;
                op[0] = __hmul2(op[0], ap[0]); op[1] = __hmul2(op[1], ap[1]);
                op[2] = __hmul2(op[2], ap[2]); op[3] = __hmul2(op[3], ap[3]);
                return o;
            };
            auto stA1 = [&](int buf, int unit, uint4 v) {
                *(uint4*)&As[buf * AS_STAGE + (unit >> 3) * ASTR + (unit & 7) * 8] = v;
            };
            // B staging via cp.async (16B), bypassing the register file
            auto cpB1 = [&](int buf, int k0, int unit) {
                int kr = unit >> 4, cc = unit & 15;
                size_t coff = (size_t)(cc >> 2) * HH + g0 + (cc & 3) * 8;
                const bf16* src = &Bw[(size_t)(k0 + kr) * G4 + coff];
                uint32_t dst = sbase +
                    (uint32_t)((BS_BASE + buf * BS_STAGE + kr * BSTR + cc * 8) * 2);
                asm volatile("cp.async.cg.shared.global [%0], [%1], 16;"
                             :: "r"(dst), "l"(src) : "memory");
            };
            auto cpB_commit = [&]() {
                asm volatile("cp.async.commit_group;" ::: "memory");
            };
            auto cpB_wait = [&]() {
                asm volatile("cp.async.wait_group 0;" ::: "memory");
            };

            FC acc[2][2];
#pragma unroll
            for (int i = 0; i < 2; i++)
#pragma unroll
                for (int j = 0; j < 2; j++) wmma::fill_fragment(acc[i][j], 0.f);

            {
                cpB1(0, 0, tid); cpB1(0, 0, tid + 256);
                cpB1(0, 0, tid + 512); cpB1(0, 0, tid + 768);
                cpB_commit();
                uint4 a0 = ldA1(0, tid), a1 = ldA1(0, tid + 256);
                stA1(0, tid, a0); stA1(0, tid + 256, a1);
                cpB_wait();
            }
            __syncthreads();
            bf16* Bs = (bf16*)smf + BS_BASE;
            for (int kt = 0; kt < KT; kt++) {
                uint4 a0, a1;
                int buf = kt & 1, nb = 1 - buf;
                if (kt + 1 < KT) {
                    int k0 = (kt + 1) * 64;
                    cpB1(nb, k0, tid); cpB1(nb, k0, tid + 256);
                    cpB1(nb, k0, tid + 512); cpB1(nb, k0, tid + 768);
                    cpB_commit();
                    a0 = ldA1(k0, tid); a1 = ldA1(k0, tid + 256);
                }
#pragma unroll
                for (int ks = 0; ks < 4; ks++) {
                    FA fa[2]; FB fb[2];
#pragma unroll
                    for (int i = 0; i < 2; i++)
                        wmma::load_matrix_sync(fa[i],
                            &As[buf * AS_STAGE + (wm * 32 + 16 * i) * ASTR + ks * 16], ASTR);
#pragma unroll
                    for (int j = 0; j < 2; j++)
                        wmma::load_matrix_sync(fb[j],
                            &Bs[buf * BS_STAGE + (ks * 16) * BSTR + wn * 32 + 16 * j], BSTR);
#pragma unroll
                    for (int i = 0; i < 2; i++)
#pragma unroll
                        for (int j = 0; j < 2; j++)
                            wmma::mma_sync(acc[i][j], fa[i], fb[j], acc[i][j]);
                }
                if (kt + 1 < KT) {
                    stA1(nb, tid, a0); stA1(nb, tid + 256, a1);
                }
                cpB_wait();
                __syncthreads();
            }
#pragma unroll
            for (int i = 0; i < 2; i++)
#pragma unroll
                for (int j = 0; j < 2; j++)
                    wmma::store_matrix_sync(&smf[(wm * 32 + 16 * i) * ZSTR + wn * 32 + 16 * j],
                                            acc[i][j], ZSTR, wmma::mem_row_major);
            __syncthreads();

            int u2 = tid & 31, rr = tid >> 5;
#pragma unroll
            for (int s = 0; s < 8; s++) {
                int r = rr * 8 + s;
                int brow = m0 + r;
                float zi, zf, zg, zo;
                if (stage == 0) {
                    size_t xb = ((size_t)brow * TT + t) * G4 + g0 + u2;
                    zi = smf[r * ZSTR + u2]      + g_xw_eco[xb];
                    zf = smf[r * ZSTR + 32 + u2] + g_xw_eco[xb + 256];
                    zg = smf[r * ZSTR + 64 + u2] + g_xw_eco[xb + 512];
                    zo = smf[r * ZSTR + 96 + u2] + g_xw_eco[xb + 768];
                } else {
                    zi = smf[r * ZSTR + u2]      + bias[g0 + u2];
                    zf = smf[r * ZSTR + 32 + u2] + bias[g0 + u2 + 256];
                    zg = smf[r * ZSTR + 64 + u2] + bias[g0 + u2 + 512];
                    zo = smf[r * ZSTR + 96 + u2] + bias[g0 + u2 + 768];
                }
                float gi = sigm(zi), gf = sigm(zf), go = sigm(zo);
                size_t sidx = (size_t)brow * HH + g0 + u2;
                float cn = gf * cst[sidx] + gi * (sig ? sigm(zg) : tanha(zg));
                float hv = go * (sig ? sigm(cn) : tanha(cn));
                cst[sidx] = cn;
                hout[sidx] = __float2bfloat16(hv);
                size_t seq = ((size_t)brow * TT + t) * HH + g0 + u2;
                if (stage == 0) {
                    g_xeb[seq] = __float2bfloat16(hv);
                } else if (stage == 1) {
                    g_oab[(size_t)jz * BT * HH + seq] = __float2bfloat16(hv);
                } else if (t % 12 == 11) {
                    g_hts[((size_t)jz * 2560 + (size_t)brow * 10 + t / 12) * HH + g0 + u2] = hv;
                }
            }
            __syncthreads();
        }
        gridbar(u);
    }
}

// ---------------- tf32 wmma GEMM (relu) for d1/d2 ----------------
__global__ void __launch_bounds__(256) k_gemm(
    const float* __restrict__ A, size_t aStride,
    const float* __restrict__ Bw, size_t bStride,
    const float* __restrict__ bias, int biasStride,
    float* __restrict__ C, size_t cStride, int N, int K)
{
    __shared__ __align__(16) float sm[8192];
    float* As = sm;
    float* Bs = sm + 4096;
    int tid = threadIdx.x, zi = blockIdx.z;
    A += (size_t)zi * aStride;
    Bw += (size_t)zi * bStride;
    bias += (size_t)zi * biasStride;
    C += (size_t)zi * cStride;
    int m0 = blockIdx.y * 128, n0 = blockIdx.x * 64;
    int arow = tid >> 2, akc = (tid & 3) * 4;
    int brow = tid >> 4, bcol = (tid & 15) * 4;

    using FA = wmma::fragment<wmma::matrix_a, 16, 16, 8, wmma::precision::tf32, wmma::row_major>;
    using FB = wmma::fragment<wmma::matrix_b, 16, 16, 8, wmma::precision::tf32, wmma::row_major>;
    using FC = wmma::fragment<wmma::accumulator, 16, 16, 8, float>;
    FC acc[2][2];
#pragma unroll
    for (int i = 0; i < 2; i++)
#pragma unroll
        for (int j = 0; j < 2; j++) wmma::fill_fragment(acc[i][j], 0.f);
    int wid = tid >> 5, wm = wid >> 1, wn = wid & 1;

    {
        float4 a0 = *(const float4*)&A[(size_t)(m0 + arow) * K + akc];
        float4 a1 = *(const float4*)&A[(size_t)(m0 + arow + 64) * K + akc];
        float4 b0 = *(const float4*)&Bw[(size_t)brow * N + n0 + bcol];
        *(float4*)&As[arow * 16 + akc] = a0;
        *(float4*)&As[(arow + 64) * 16 + akc] = a1;
        *(float4*)&Bs[brow * 64 + bcol] = b0;
    }
    __syncthreads();
    int KT = K / 16;
    for (int kt = 0; kt < KT; kt++) {
        float4 a0, a1, b0;
        if (kt + 1 < KT) {
            int k0 = (kt + 1) * 16;
            a0 = *(const float4*)&A[(size_t)(m0 + arow) * K + k0 + akc];
            a1 = *(const float4*)&A[(size_t)(m0 + arow + 64) * K + k0 + akc];
            b0 = *(const float4*)&Bw[(size_t)(k0 + brow) * N + n0 + bcol];
        }
        int buf = kt & 1;
#pragma unroll
        for (int ks = 0; ks < 2; ks++) {
            FA fa[2]; FB fb[2];
#pragma unroll
            for (int i = 0; i < 2; i++) {
                wmma::load_matrix_sync(fa[i], &As[buf * 2048 + (wm * 32 + 16 * i) * 16 + ks * 8], 16);
#pragma unroll
                for (int e = 0; e < fa[i].num_elements; e++) fa[i].x[e] = wmma::__float_to_tf32(fa[i].x[e]);
            }
#pragma unroll
            for (int j = 0; j < 2; j++) {
                wmma::load_matrix_sync(fb[j], &Bs[buf * 1024 + (ks * 8) * 64 + wn * 32 + 16 * j], 64);
#pragma unroll
                for (int e = 0; e < fb[j].num_elements; e++) fb[j].x[e] = wmma::__float_to_tf32(fb[j].x[e]);
            }
#pragma unroll
            for (int i = 0; i < 2; i++)
#pragma unroll
                for (int j = 0; j < 2; j++) wmma::mma_sync(acc[i][j], fa[i], fb[j], acc[i][j]);
        }
        if (kt + 1 < KT) {
            int nb = 1 - buf;
            *(float4*)&As[nb * 2048 + arow * 16 + akc] = a0;
            *(float4*)&As[nb * 2048 + (arow + 64) * 16 + akc] = a1;
            *(float4*)&Bs[nb * 1024 + brow * 64 + bcol] = b0;
        }
        __syncthreads();
    }
#pragma unroll
    for (int i = 0; i < 2; i++)
#pragma unroll
        for (int j = 0; j < 2; j++)
            wmma::store_matrix_sync(&sm[(wm * 32 + 16 * i) * 64 + wn * 32 + 16 * j], acc[i][j], 64,
                                    wmma::mem_row_major);
    __syncthreads();
    int col = tid & 63, r0i = tid >> 6;
    float bv = bias[n0 + col];
#pragma unroll 8
    for (int s = 0; s < 32; s++) {
        int r = r0i + s * 4;
        float v = sm[r * 64 + col] + bv;
        C[(size_t)(m0 + r) * N + n0 + col] = fmaxf(v, 0.f);
    }
}

// ---------------- head ----------------
__global__ void k_head(const float* __restrict__ inp, const float* __restrict__ dfW,
                       const float* __restrict__ dfb, float* __restrict__ out) {
    int gid = blockIdx.x * blockDim.x + threadIdx.x;
    if (gid >= 2560 * 7) return;
    int j = gid % 7, bt = gid / 7, b = bt / 10;
    const float* w = dfW + j * 67;
    const float* v = &g_d2[((size_t)j * 2560 + bt) * 64];
    float s = dfb[j];
#pragma unroll 16
    for (int k = 0; k < 64; k++) s += v[k] * w[k];
    size_t base = ((size_t)b * TT + 11) * DIN;
    s += inp[base + 23] * w[64] + inp[base + 23 + j + 1] * w[65] + inp[base + 23 + j + 8] * w[66];
    s += inp[base + 16 + j];
    out[(size_t)bt * 7 + j] = fmaxf(s, LS_MAX_c[j]);
}

extern "C" void kernel_launch(void* const* d_in, const int* in_sizes, int n_in,
                              void* d_out, int out_size) {
    const float* inp    = (const float*)d_in[0];
    const float* eco_W  = (const float*)d_in[1];
    const float* eco_U  = (const float*)d_in[2];
    const float* eco_b  = (const float*)d_in[3];
    const float* data_W = (const float*)d_in[4];
    const float* data_U = (const float*)d_in[5];
    const float* data_b = (const float*)d_in[6];
    const float* att_W  = (const float*)d_in[7];
    const float* att_U  = (const float*)d_in[8];
    const float* att_b  = (const float*)d_in[9];
    const float* ts_W   = (const float*)d_in[10];
    const float* ts_U   = (const float*)d_in[11];
    const float* ts_b   = (const float*)d_in[12];
    const float* d1_W   = (const float*)d_in[13];
    const float* d1_b   = (const float*)d_in[14];
    const float* d2_W   = (const float*)d_in[15];
    const float* d2_b   = (const float*)d_in[16];
    const float* df_W   = (const float*)d_in[17];
    const float* df_b   = (const float*)d_in[18];
    float* out = (float*)d_out;

    float *hts, *d1, *d2;
    cudaGetSymbolAddress((void**)&hts, g_hts);
    cudaGetSymbolAddress((void**)&d1, g_d1);
    cudaGetSymbolAddress((void**)&d2, g_d2);

    cudaFuncSetAttribute(k_persist, cudaFuncAttributeMaxDynamicSharedMemorySize,
                         SMEM_FLOATS * 4);

    // k_persist is the 4th launch (ncu capture window)
    k_zero<<<64, 256>>>();
    k_xw_eco<<<BT / 8, 256>>>(inp, eco_W, eco_b);
    k_packall<<<44032, 256>>>(eco_U, data_U, data_W, att_U, att_W, ts_U, ts_W);

    k_persist<<<NCTA, 256, SMEM_FLOATS * 4>>>(data_b, att_b, ts_b);

    k_gemm<<<dim3(4, 20, 7), 256>>>(hts, (size_t)2560 * HH, d1_W, (size_t)HH * 256,
                                    d1_b, 256, d1, (size_t)2560 * 256, 256, HH);
    k_gemm<<<dim3(1, 20, 7), 256>>>(d1, (size_t)2560 * 256, d2_W, (size_t)256 * 64,
                                    d2_b, 64, d2, (size_t)2560 * 64, 64, 256);
    k_head<<<70, 256>>>(inp, df_W, df_b, out);
}